// round 13
// baseline (speedup 1.0000x reference)
#include <cuda_runtime.h>
#include <cuda_fp16.h>
#include <stdint.h>

// ---------------- problem constants ----------------
#define B_    2048
#define V_    2
#define D_    256
#define NTOT  4096
#define NB_   32              // 128-wide blocks per dimension
#define NTILES 528            // NB*(NB+1)/2 upper-triangular tiles
#define NPREP  256            // producer CTAs for the prep phase
#define GAMMA_F   0.9f
#define TEMP_F    0.07f
#define BASET_F   0.07f

// ---------------- device scratch ----------------
__device__ __half g_Fh[NTOT * D_];
__device__ float g_Mp[NB_ * NTOT];
__device__ float g_Ap[NB_ * NTOT];
__device__ float g_Wp[NB_ * NTOT];
__device__ float g_SP[NTOT];
__device__ float g_Lp[8];
__device__ unsigned int g_prep;    // prep done counter
__device__ unsigned int g_ctr;     // GEMM done counter
__device__ unsigned int g_fin;     // combine finish ticket

// ---------------- helpers ----------------
__device__ __forceinline__ uint32_t smem_u32(const void* p) {
    uint32_t a;
    asm("{ .reg .u64 t; cvta.to.shared.u64 t, %1; cvt.u32.u64 %0, t; }" : "=r"(a) : "l"(p));
    return a;
}
__device__ __forceinline__ uint32_t sw128(uint32_t off) {
    return off ^ ((off >> 3) & 0x70);
}
__device__ __forceinline__ void ldsm_x4(uint32_t* r, uint32_t addr) {
    asm volatile("ldmatrix.sync.aligned.m8n8.x4.shared.b16 {%0,%1,%2,%3}, [%4];"
                 : "=r"(r[0]), "=r"(r[1]), "=r"(r[2]), "=r"(r[3]) : "r"(addr));
}
__device__ __forceinline__ void mma_f16(float* c, const uint32_t* a, uint32_t b0, uint32_t b1) {
    asm volatile("mma.sync.aligned.m16n8k16.row.col.f32.f16.f16.f32 "
                 "{%0,%1,%2,%3}, {%4,%5,%6,%7}, {%8,%9}, {%0,%1,%2,%3};"
                 : "+f"(c[0]), "+f"(c[1]), "+f"(c[2]), "+f"(c[3])
                 : "r"(a[0]), "r"(a[1]), "r"(a[2]), "r"(a[3]), "r"(b0), "r"(b1));
}
__device__ __forceinline__ void cp16(uint32_t saddr, const void* gptr) {
    asm volatile("cp.async.cg.shared.global [%0], [%1], 16;"
                 :: "r"(saddr), "l"(__cvta_generic_to_global(gptr)));
}
#define CP_COMMIT() asm volatile("cp.async.commit_group;" ::: "memory")
#define CP_WAIT(n)  asm volatile("cp.async.wait_group %0;" :: "n"(n) : "memory")
__device__ __forceinline__ unsigned int ld_cg_u32(const unsigned int* p) {
    unsigned int v;
    asm volatile("ld.global.cg.u32 %0, [%1];" : "=r"(v) : "l"(p));
    return v;
}

// ---------------- single fused kernel, 512 threads ----------------
#define OFF_A 0
#define OFF_B 16384
#define STAGE_BYTES 32768
#define SMEM_BYTES  (2 * STAGE_BYTES)

__global__ void __launch_bounds__(512, 2) fused_kernel(const float* __restrict__ feats,
                                                       const int* __restrict__ index,
                                                       const float* __restrict__ u,
                                                       float* __restrict__ out) {
    extern __shared__ char smem[];
    const uint32_t sb = smem_u32(smem);
    const int tid  = threadIdx.x;
    const int lane = tid & 31;
    const int wid  = tid >> 5;      // 0..15
    const int wm   = wid & 3;       // M quarter (32 rows)
    const int wn   = wid >> 2;      // N quarter (32 cols)

    // ---------------- phase 0: prep (producer CTAs bid < 256, all wave-1) ----------------
    if (blockIdx.x < NPREP) {
#pragma unroll
        for (int it = 0; it < 2; it++) {
            int e = (blockIdx.x * 1024 + it * 512 + tid) * 4;
            int n = e >> 8;
            int d = e & 255;
            int v = n >> 11;
            int b = n & 2047;
            float4 f = *(const float4*)&feats[((b << 1) | v) * D_ + d];
            uint2 hp;
            hp.x = ((uint32_t)__half_as_ushort(__float2half(f.y)) << 16) | __half_as_ushort(__float2half(f.x));
            hp.y = ((uint32_t)__half_as_ushort(__float2half(f.w)) << 16) | __half_as_ushort(__float2half(f.z));
            *(uint2*)&g_Fh[e] = hp;
        }
        __threadfence();
        __syncthreads();
        if (tid == 0) atomicAdd(&g_prep, 1u);
    }
    // all CTAs wait for the full fp16 matrix
    if (tid == 0) {
        while (ld_cg_u32(&g_prep) < (unsigned)NPREP) { __nanosleep(60); }
    }
    __syncthreads();
    __threadfence();

    // decode upper-triangular tile (bi, bj), bi <= bj
    int bi = 0, rem = blockIdx.x;
    while (rem >= (NB_ - bi)) { rem -= (NB_ - bi); bi++; }
    const int bj = bi + rem;
    const int row0 = bi * 128;
    const int col0 = bj * 128;

    // staging coords: 1024 16B-chunks per tile / 512 threads = 2 each
    int sr[2], sc[2];
    uint32_t ssw[2];
#pragma unroll
    for (int it = 0; it < 2; it++) {
        int q = tid + it * 512;
        sr[it] = q >> 3;
        sc[it] = q & 7;
        ssw[it] = sw128((uint32_t)(sr[it] * 128 + sc[it] * 16));
    }

    // prefetch chunk 0 into stage 0
#pragma unroll
    for (int it = 0; it < 2; it++) {
        cp16(sb + OFF_A + ssw[it], &g_Fh[(row0 + sr[it]) * D_ + sc[it] * 8]);
        cp16(sb + OFF_B + ssw[it], &g_Fh[(col0 + sr[it]) * D_ + sc[it] * 8]);
    }
    CP_COMMIT();

    float acc[2][4][4];
#pragma unroll
    for (int mi = 0; mi < 2; mi++)
#pragma unroll
        for (int nj = 0; nj < 4; nj++)
#pragma unroll
            for (int c = 0; c < 4; c++) acc[mi][nj][c] = 0.0f;

    const int arow  = wm * 32 + (lane & 7) + ((lane >> 3) & 1) * 8;
    const int akc0  = (lane >> 4) * 8;
    const int brow  = wn * 32 + (lane & 7) + (lane >> 4) * 8;
    const int bkc0  = ((lane >> 3) & 1) * 8;

    for (int kc = 0; kc < 4; kc++) {
        if (kc < 3) {
            uint32_t nb = sb + ((kc + 1) & 1) * STAGE_BYTES;
#pragma unroll
            for (int it = 0; it < 2; it++) {
                cp16(nb + OFF_A + ssw[it], &g_Fh[(row0 + sr[it]) * D_ + (kc + 1) * 64 + sc[it] * 8]);
                cp16(nb + OFF_B + ssw[it], &g_Fh[(col0 + sr[it]) * D_ + (kc + 1) * 64 + sc[it] * 8]);
            }
            CP_COMMIT();
            CP_WAIT(1);
        } else {
            CP_WAIT(0);
        }
        __syncthreads();

        const uint32_t cb = sb + (kc & 1) * STAGE_BYTES;
#pragma unroll
        for (int ks = 0; ks < 4; ks++) {
            const int akc = ks * 16 + akc0;
            const int bkc = ks * 16 + bkc0;
            uint32_t a[2][4], b[2][4];
#pragma unroll
            for (int mi = 0; mi < 2; mi++)
                ldsm_x4(a[mi], cb + OFF_A + sw128((uint32_t)((arow + mi * 16) * 128 + akc * 2)));
#pragma unroll
            for (int b2 = 0; b2 < 2; b2++)
                ldsm_x4(b[b2], cb + OFF_B + sw128((uint32_t)((brow + b2 * 16) * 128 + bkc * 2)));
#pragma unroll
            for (int mi = 0; mi < 2; mi++)
#pragma unroll
                for (int nj = 0; nj < 4; nj++) {
                    uint32_t b0 = (nj & 1) ? b[nj >> 1][2] : b[nj >> 1][0];
                    uint32_t b1 = (nj & 1) ? b[nj >> 1][3] : b[nj >> 1][1];
                    mma_f16(acc[mi][nj], a[mi], b0, b1);
                }
        }
        __syncthreads();
    }

    // ---------------- epilogue: row/col stats ----------------
    float* redm = (float*)smem;          // [128][4] row partials (merge over wn)
    float* reda = redm + 512;
    float* redw = reda + 512;
    float* colm = redw + 512;            // [128][4] col partials (merge over wm)
    float* cola = colm + 512;
    float* colw = cola + 512;
    const float invT = 1.0f / TEMP_F;

    // --- row pass: rows of block bi over cols of block bj ---
#pragma unroll
    for (int mi = 0; mi < 2; mi++) {
#pragma unroll
        for (int h = 0; h < 2; h++) {
            int lr = wm * 32 + mi * 16 + h * 8 + (lane >> 2);
            int gi = row0 + lr;
            int posj = (gi + B_) & (NTOT - 1);
            float s[8];
#pragma unroll
            for (int nj = 0; nj < 4; nj++) {
                s[nj * 2]     = acc[mi][nj][h * 2]     * invT;
                s[nj * 2 + 1] = acc[mi][nj][h * 2 + 1] * invT;
            }
            float m = s[0];
#pragma unroll
            for (int i2 = 1; i2 < 8; i2++) m = fmaxf(m, s[i2]);
            m = fmaxf(m, __shfl_xor_sync(0xffffffffu, m, 1));
            m = fmaxf(m, __shfl_xor_sync(0xffffffffu, m, 2));
            float A = 0.0f, W = 0.0f;
#pragma unroll
            for (int nj = 0; nj < 4; nj++) {
#pragma unroll
                for (int c = 0; c < 2; c++) {
                    int gj = col0 + wn * 32 + nj * 8 + (lane & 3) * 2 + c;
                    float v = s[nj * 2 + c];
                    if (gj == posj) {
                        g_SP[gi] = v;
                    } else {
                        float e = __expf(v - m);
                        A += e;
                        W += e * (v - m);
                    }
                }
            }
            A += __shfl_xor_sync(0xffffffffu, A, 1);
            A += __shfl_xor_sync(0xffffffffu, A, 2);
            W += __shfl_xor_sync(0xffffffffu, W, 1);
            W += __shfl_xor_sync(0xffffffffu, W, 2);
            if ((lane & 3) == 0) {
                redm[lr * 4 + wn] = m;
                reda[lr * 4 + wn] = A;
                redw[lr * 4 + wn] = W;
            }
        }
    }

    // --- col pass (off-diagonal): rows of block bj over cols of block bi ---
    if (bi != bj) {
#pragma unroll
        for (int nj = 0; nj < 4; nj++) {
#pragma unroll
            for (int cbx = 0; cbx < 2; cbx++) {
                int cid = wn * 32 + nj * 8 + (lane & 3) * 2 + cbx;
                int gj = col0 + cid;
                int posi = (gj + B_) & (NTOT - 1);
                float sv[4];
#pragma unroll
                for (int mi = 0; mi < 2; mi++) {
                    sv[mi * 2]     = acc[mi][nj][cbx]     * invT;
                    sv[mi * 2 + 1] = acc[mi][nj][2 + cbx] * invT;
                }
                float m = sv[0];
#pragma unroll
                for (int i2 = 1; i2 < 4; i2++) m = fmaxf(m, sv[i2]);
                m = fmaxf(m, __shfl_xor_sync(0xffffffffu, m, 4));
                m = fmaxf(m, __shfl_xor_sync(0xffffffffu, m, 8));
                m = fmaxf(m, __shfl_xor_sync(0xffffffffu, m, 16));
                float A = 0.0f, W = 0.0f;
#pragma unroll
                for (int mi = 0; mi < 2; mi++) {
#pragma unroll
                    for (int h = 0; h < 2; h++) {
                        int gi = row0 + wm * 32 + mi * 16 + h * 8 + (lane >> 2);
                        float v = sv[mi * 2 + h];
                        if (gi == posi) {
                            g_SP[gj] = v;          // S symmetric
                        } else {
                            float e = __expf(v - m);
                            A += e;
                            W += e * (v - m);
                        }
                    }
                }
                A += __shfl_xor_sync(0xffffffffu, A, 4);
                A += __shfl_xor_sync(0xffffffffu, A, 8);
                A += __shfl_xor_sync(0xffffffffu, A, 16);
                W += __shfl_xor_sync(0xffffffffu, W, 4);
                W += __shfl_xor_sync(0xffffffffu, W, 8);
                W += __shfl_xor_sync(0xffffffffu, W, 16);
                if ((lane >> 2) == 0) {
                    colm[cid * 4 + wm] = m;
                    cola[cid * 4 + wm] = A;
                    colw[cid * 4 + wm] = W;
                }
            }
        }
    }

    __syncthreads();
    if (tid < 128) {
        float mm = redm[tid * 4], aa = reda[tid * 4], ww = redw[tid * 4];
#pragma unroll
        for (int t = 1; t < 4; t++) {
            float m2 = redm[tid * 4 + t];
            float a2 = reda[tid * 4 + t];
            float w2 = redw[tid * 4 + t];
            float mN = fmaxf(mm, m2);
            float c1 = __expf(mm - mN);
            float c2 = __expf(m2 - mN);
            ww = c1 * (ww + (mm - mN) * aa) + c2 * (w2 + (m2 - mN) * a2);
            aa = c1 * aa + c2 * a2;
            mm = mN;
        }
        g_Mp[bj * NTOT + row0 + tid] = mm;
        g_Ap[bj * NTOT + row0 + tid] = aa;
        g_Wp[bj * NTOT + row0 + tid] = ww;
    } else if (bi != bj && tid < 256) {
        int cid = tid - 128;
        float mm = colm[cid * 4], aa = cola[cid * 4], ww = colw[cid * 4];
#pragma unroll
        for (int t = 1; t < 4; t++) {
            float m2 = colm[cid * 4 + t];
            float a2 = cola[cid * 4 + t];
            float w2 = colw[cid * 4 + t];
            float mN = fmaxf(mm, m2);
            float c1 = __expf(mm - mN);
            float c2 = __expf(m2 - mN);
            ww = c1 * (ww + (mm - mN) * aa) + c2 * (w2 + (m2 - mN) * a2);
            aa = c1 * aa + c2 * a2;
            mm = mN;
        }
        g_Mp[bi * NTOT + col0 + cid] = mm;
        g_Ap[bi * NTOT + col0 + cid] = aa;
        g_Wp[bi * NTOT + col0 + cid] = ww;
    }

    // ---------------- done-ticket + fused combine (CTAs 0..7) ----------------
    __threadfence();          // each thread: make its global writes visible
    __syncthreads();
    if (tid == 0) atomicAdd(&g_ctr, 1u);

    if (blockIdx.x < 8) {
        if (tid == 0) {
            while (ld_cg_u32(&g_ctr) < (unsigned)NTILES) { __nanosleep(100); }
        }
        __syncthreads();
        __threadfence();      // acquire: see all partials

        __shared__ float red[8];
        float val = 0.0f;
        if (tid < 256) {
            int b = blockIdx.x * 256 + tid;            // [0, 2048)
            float m1 = -1e30f, a1 = 0.0f, w1 = 0.0f;   // row b
            float m2 = -1e30f, a2 = 0.0f, w2 = 0.0f;   // row b+2048
#pragma unroll
            for (int s = 0; s < NB_; s++) {
                {
                    float mx = g_Mp[s * NTOT + b];
                    float ax = g_Ap[s * NTOT + b];
                    float wx = g_Wp[s * NTOT + b];
                    float mN = fmaxf(m1, mx);
                    float c1 = __expf(m1 - mN);
                    float c2 = __expf(mx - mN);
                    w1 = c1 * (w1 + (m1 - mN) * a1) + c2 * (wx + (mx - mN) * ax);
                    a1 = c1 * a1 + c2 * ax;
                    m1 = mN;
                }
                {
                    float mx = g_Mp[s * NTOT + B_ + b];
                    float ax = g_Ap[s * NTOT + B_ + b];
                    float wx = g_Wp[s * NTOT + B_ + b];
                    float mN = fmaxf(m2, mx);
                    float c1 = __expf(m2 - mN);
                    float c2 = __expf(mx - mN);
                    w2 = c1 * (w2 + (m2 - mN) * a2) + c2 * (wx + (mx - mN) * ax);
                    a2 = c1 * a2 + c2 * ax;
                    m2 = mN;
                }
            }
            float u_new = (1.0f - GAMMA_F) * u[index[b]] + GAMMA_F * a1;
            const float k = -(TEMP_F / BASET_F) * (1.0f / (float)NTOT);
            val = k * (((g_SP[b] - m1) - w1 / u_new) +
                       ((g_SP[B_ + b] - m2) - w2 / u_new));
        }
#pragma unroll
        for (int o = 16; o; o >>= 1) val += __shfl_down_sync(0xffffffffu, val, o);
        if (tid < 256 && (tid & 31) == 0) red[tid >> 5] = val;
        __syncthreads();
        if (tid < 8) {
            float v = red[tid];
#pragma unroll
            for (int o = 4; o; o >>= 1) v += __shfl_down_sync(0xffu, v, o);
            if (tid == 0) {
                g_Lp[blockIdx.x] = v;
                __threadfence();
                unsigned int t = atomicAdd(&g_fin, 1u);
                if (t == 7u) {                     // last combiner: final sum + counter reset
                    float s = 0.0f;
#pragma unroll
                    for (int i = 0; i < 8; i++) s += g_Lp[i];
                    out[0] = s;
                    g_prep = 0;                    // self-reset for next graph replay
                    g_ctr  = 0;
                    g_fin  = 0;
                }
            }
        }
    }
}

// ---------------- launch ----------------
extern "C" void kernel_launch(void* const* d_in, const int* in_sizes, int n_in,
                              void* d_out, int out_size) {
    const int*   d_index = nullptr;
    const float* d_feats = nullptr;
    const float* d_u     = nullptr;
    for (int i = 0; i < n_in; i++) {
        if (in_sizes[i] == B_)                 d_index = (const int*)d_in[i];
        else if (in_sizes[i] == B_ * V_ * D_)  d_feats = (const float*)d_in[i];
        else                                   d_u     = (const float*)d_in[i];
    }
    float* out = (float*)d_out;

    cudaFuncSetAttribute(fused_kernel,
                         cudaFuncAttributeMaxDynamicSharedMemorySize, SMEM_BYTES);

    fused_kernel<<<NTILES, 512, SMEM_BYTES>>>(d_feats, d_index, d_u, out);
}

// round 14
// speedup vs baseline: 1.1730x; 1.1730x over previous
#include <cuda_runtime.h>
#include <cuda_fp16.h>
#include <stdint.h>

// ---------------- problem constants ----------------
#define B_    2048
#define V_    2
#define D_    256
#define NTOT  4096
#define NB_   32              // 128-wide blocks per dimension
#define NTILES 528            // NB*(NB+1)/2 upper-triangular tiles
#define NPREP  256            // producer CTAs for the prep phase
#define GAMMA_F   0.9f
#define TEMP_F    0.07f
#define BASET_F   0.07f

// ---------------- device scratch ----------------
__device__ __half g_Fh[NTOT * D_];
__device__ float g_Mp[NB_ * NTOT];   // per-(slot,row) raw max
__device__ float g_Ep[NB_ * NTOT];   // per-(slot,row) sum e,  e = exp((raw-1)/T)
__device__ float g_Gp[NB_ * NTOT];   // per-(slot,row) sum e*raw
__device__ float g_SP[NTOT];         // raw positive logit
__device__ float g_Lp[8];
__device__ unsigned int g_prep;
__device__ unsigned int g_ctr;
__device__ unsigned int g_fin;

// ---------------- helpers ----------------
__device__ __forceinline__ uint32_t smem_u32(const void* p) {
    uint32_t a;
    asm("{ .reg .u64 t; cvta.to.shared.u64 t, %1; cvt.u32.u64 %0, t; }" : "=r"(a) : "l"(p));
    return a;
}
__device__ __forceinline__ uint32_t sw128(uint32_t off) {
    return off ^ ((off >> 3) & 0x70);
}
__device__ __forceinline__ void ldsm_x4(uint32_t* r, uint32_t addr) {
    asm volatile("ldmatrix.sync.aligned.m8n8.x4.shared.b16 {%0,%1,%2,%3}, [%4];"
                 : "=r"(r[0]), "=r"(r[1]), "=r"(r[2]), "=r"(r[3]) : "r"(addr));
}
__device__ __forceinline__ void mma_f16(float* c, const uint32_t* a, uint32_t b0, uint32_t b1) {
    asm volatile("mma.sync.aligned.m16n8k16.row.col.f32.f16.f16.f32 "
                 "{%0,%1,%2,%3}, {%4,%5,%6,%7}, {%8,%9}, {%0,%1,%2,%3};"
                 : "+f"(c[0]), "+f"(c[1]), "+f"(c[2]), "+f"(c[3])
                 : "r"(a[0]), "r"(a[1]), "r"(a[2]), "r"(a[3]), "r"(b0), "r"(b1));
}
__device__ __forceinline__ void cp16(uint32_t saddr, const void* gptr) {
    asm volatile("cp.async.cg.shared.global [%0], [%1], 16;"
                 :: "r"(saddr), "l"(__cvta_generic_to_global(gptr)));
}
#define CP_COMMIT() asm volatile("cp.async.commit_group;" ::: "memory")
#define CP_WAIT(n)  asm volatile("cp.async.wait_group %0;" :: "n"(n) : "memory")
__device__ __forceinline__ unsigned int ld_cg_u32(const unsigned int* p) {
    unsigned int v;
    asm volatile("ld.global.cg.u32 %0, [%1];" : "=r"(v) : "l"(p));
    return v;
}

// ---------------- single fused kernel, 256 threads (R10 mainloop) ----------------
#define OFF_A 0
#define OFF_B 16384
#define STAGE_BYTES 32768
#define SMEM_BYTES  (2 * STAGE_BYTES)

__global__ void __launch_bounds__(256, 2) fused_kernel(const float* __restrict__ feats,
                                                       const int* __restrict__ index,
                                                       const float* __restrict__ u,
                                                       float* __restrict__ out) {
    extern __shared__ char smem[];
    const uint32_t sb = smem_u32(smem);
    const int tid  = threadIdx.x;
    const int lane = tid & 31;
    const int wid  = tid >> 5;
    const int wm   = wid & 1;       // M half (64 rows)
    const int wn   = wid >> 1;      // N quarter (32 cols)

    // ---------------- phase 0: prep (producer CTAs bid < 256, all wave-1) ----------------
    if (blockIdx.x < NPREP) {
#pragma unroll
        for (int it = 0; it < 4; it++) {
            int e = (blockIdx.x * 1024 + it * 256 + tid) * 4;
            int n = e >> 8;
            int d = e & 255;
            int v = n >> 11;
            int b = n & 2047;
            float4 f = *(const float4*)&feats[((b << 1) | v) * D_ + d];
            uint2 hp;
            hp.x = ((uint32_t)__half_as_ushort(__float2half(f.y)) << 16) | __half_as_ushort(__float2half(f.x));
            hp.y = ((uint32_t)__half_as_ushort(__float2half(f.w)) << 16) | __half_as_ushort(__float2half(f.z));
            *(uint2*)&g_Fh[e] = hp;
        }
        __threadfence();
        __syncthreads();
        if (tid == 0) atomicAdd(&g_prep, 1u);
    }
    if (tid == 0) {
        while (ld_cg_u32(&g_prep) < (unsigned)NPREP) { __nanosleep(60); }
    }
    __syncthreads();
    __threadfence();

    // decode upper-triangular tile (bi, bj), bi <= bj
    int bi = 0, rem = blockIdx.x;
    while (rem >= (NB_ - bi)) { rem -= (NB_ - bi); bi++; }
    const int bj = bi + rem;
    const int row0 = bi * 128;
    const int col0 = bj * 128;

    // staging coords
    int sr[4], sc[4];
    uint32_t ssw[4];
#pragma unroll
    for (int it = 0; it < 4; it++) {
        int q = tid + it * 256;
        sr[it] = q >> 3;
        sc[it] = q & 7;
        ssw[it] = sw128((uint32_t)(sr[it] * 128 + sc[it] * 16));
    }

    // prefetch chunk 0 into stage 0
#pragma unroll
    for (int it = 0; it < 4; it++) {
        cp16(sb + OFF_A + ssw[it], &g_Fh[(row0 + sr[it]) * D_ + sc[it] * 8]);
        cp16(sb + OFF_B + ssw[it], &g_Fh[(col0 + sr[it]) * D_ + sc[it] * 8]);
    }
    CP_COMMIT();

    float acc[4][4][4];
#pragma unroll
    for (int mi = 0; mi < 4; mi++)
#pragma unroll
        for (int nj = 0; nj < 4; nj++)
#pragma unroll
            for (int c = 0; c < 4; c++) acc[mi][nj][c] = 0.0f;

    const int arow  = wm * 64 + (lane & 7) + ((lane >> 3) & 1) * 8;
    const int akc0  = (lane >> 4) * 8;
    const int brow  = wn * 32 + (lane & 7) + (lane >> 4) * 8;
    const int bkc0  = ((lane >> 3) & 1) * 8;

    for (int kc = 0; kc < 4; kc++) {
        if (kc < 3) {
            uint32_t nb = sb + ((kc + 1) & 1) * STAGE_BYTES;
#pragma unroll
            for (int it = 0; it < 4; it++) {
                cp16(nb + OFF_A + ssw[it], &g_Fh[(row0 + sr[it]) * D_ + (kc + 1) * 64 + sc[it] * 8]);
                cp16(nb + OFF_B + ssw[it], &g_Fh[(col0 + sr[it]) * D_ + (kc + 1) * 64 + sc[it] * 8]);
            }
            CP_COMMIT();
            CP_WAIT(1);
        } else {
            CP_WAIT(0);
        }
        __syncthreads();

        const uint32_t cb = sb + (kc & 1) * STAGE_BYTES;
#pragma unroll
        for (int ks = 0; ks < 4; ks++) {
            const int akc = ks * 16 + akc0;
            const int bkc = ks * 16 + bkc0;
            uint32_t a[4][4], b[2][4];
#pragma unroll
            for (int mi = 0; mi < 4; mi++)
                ldsm_x4(a[mi], cb + OFF_A + sw128((uint32_t)((arow + mi * 16) * 128 + akc * 2)));
#pragma unroll
            for (int b2 = 0; b2 < 2; b2++)
                ldsm_x4(b[b2], cb + OFF_B + sw128((uint32_t)((brow + b2 * 16) * 128 + bkc * 2)));
#pragma unroll
            for (int mi = 0; mi < 4; mi++)
#pragma unroll
                for (int nj = 0; nj < 4; nj++) {
                    uint32_t b0 = (nj & 1) ? b[nj >> 1][2] : b[nj >> 1][0];
                    uint32_t b1 = (nj & 1) ? b[nj >> 1][3] : b[nj >> 1][1];
                    mma_f16(acc[mi][nj], a[mi], b0, b1);
                }
        }
        __syncthreads();
    }

    // ---------------- epilogue: fused row+col stats, fixed-m0 exp ----------------
    // e = exp((raw - 1)/T); row/col share e. acc values are RAW dot products.
    float* redm = (float*)smem;          // [128][4] row partials
    float* rede = redm + 512;
    float* redg = rede + 512;
    float* colm_s = redg + 512;          // [128][2] col partials
    float* cole_s = colm_s + 256;
    float* colg_s = cole_s + 256;
    const float invT = 1.0f / TEMP_F;
    const bool offd = (bi != bj);

    float colE[8], colG[8], colM[8];
#pragma unroll
    for (int k = 0; k < 8; k++) { colE[k] = 0.0f; colG[k] = 0.0f; colM[k] = -1e30f; }

#pragma unroll
    for (int mi = 0; mi < 4; mi++) {
#pragma unroll
        for (int h = 0; h < 2; h++) {
            int lr = wm * 64 + mi * 16 + h * 8 + (lane >> 2);
            int gi = row0 + lr;
            int posj = (gi + B_) & (NTOT - 1);
            float rE = 0.0f, rG = 0.0f, rM = -1e30f;
#pragma unroll
            for (int nj = 0; nj < 4; nj++) {
#pragma unroll
                for (int c = 0; c < 2; c++) {
                    const int k = nj * 2 + c;
                    float raw = acc[mi][nj][h * 2 + c];
                    int gj = col0 + wn * 32 + nj * 8 + (lane & 3) * 2 + c;
                    rM = fmaxf(rM, raw);
                    if (offd) colM[k] = fmaxf(colM[k], raw);
                    if (gj == posj) {
                        g_SP[gi] = raw;                  // row gi's positive
                        g_SP[gj] = raw;                  // row gj's positive (symmetric)
                    } else {
                        float e = __expf((raw - 1.0f) * invT);
                        rE += e;
                        rG = fmaf(e, raw, rG);
                        if (offd) {
                            colE[k] += e;
                            colG[k] = fmaf(e, raw, colG[k]);
                        }
                    }
                }
            }
            rM = fmaxf(rM, __shfl_xor_sync(0xffffffffu, rM, 1));
            rM = fmaxf(rM, __shfl_xor_sync(0xffffffffu, rM, 2));
            rE += __shfl_xor_sync(0xffffffffu, rE, 1);
            rE += __shfl_xor_sync(0xffffffffu, rE, 2);
            rG += __shfl_xor_sync(0xffffffffu, rG, 1);
            rG += __shfl_xor_sync(0xffffffffu, rG, 2);
            if ((lane & 3) == 0) {
                redm[lr * 4 + wn] = rM;
                rede[lr * 4 + wn] = rE;
                redg[lr * 4 + wn] = rG;
            }
        }
    }

    if (offd) {
#pragma unroll
        for (int k = 0; k < 8; k++) {
            int cid = wn * 32 + (k >> 1) * 8 + (lane & 3) * 2 + (k & 1);
            float m = colM[k], E = colE[k], G = colG[k];
            m = fmaxf(m, __shfl_xor_sync(0xffffffffu, m, 4));
            m = fmaxf(m, __shfl_xor_sync(0xffffffffu, m, 8));
            m = fmaxf(m, __shfl_xor_sync(0xffffffffu, m, 16));
            E += __shfl_xor_sync(0xffffffffu, E, 4);
            E += __shfl_xor_sync(0xffffffffu, E, 8);
            E += __shfl_xor_sync(0xffffffffu, E, 16);
            G += __shfl_xor_sync(0xffffffffu, G, 4);
            G += __shfl_xor_sync(0xffffffffu, G, 8);
            G += __shfl_xor_sync(0xffffffffu, G, 16);
            if ((lane >> 2) == 0) {
                colm_s[cid * 2 + wm] = m;
                cole_s[cid * 2 + wm] = E;
                colg_s[cid * 2 + wm] = G;
            }
        }
    }

    __syncthreads();
    if (tid < 128) {
        float mm = redm[tid * 4], ee = rede[tid * 4], gg = redg[tid * 4];
#pragma unroll
        for (int t = 1; t < 4; t++) {
            mm = fmaxf(mm, redm[tid * 4 + t]);
            ee += rede[tid * 4 + t];
            gg += redg[tid * 4 + t];
        }
        g_Mp[bj * NTOT + row0 + tid] = mm;
        g_Ep[bj * NTOT + row0 + tid] = ee;
        g_Gp[bj * NTOT + row0 + tid] = gg;
    } else if (offd && tid < 256) {
        int cid = tid - 128;
        float mm = fmaxf(colm_s[cid * 2], colm_s[cid * 2 + 1]);
        float ee = cole_s[cid * 2] + cole_s[cid * 2 + 1];
        float gg = colg_s[cid * 2] + colg_s[cid * 2 + 1];
        g_Mp[bi * NTOT + col0 + cid] = mm;
        g_Ep[bi * NTOT + col0 + cid] = ee;
        g_Gp[bi * NTOT + col0 + cid] = gg;
    }

    // ---------------- done-ticket + fused combine (CTAs 0..7) ----------------
    __threadfence();
    __syncthreads();
    if (tid == 0) atomicAdd(&g_ctr, 1u);

    if (blockIdx.x < 8) {
        if (tid == 0) {
            while (ld_cg_u32(&g_ctr) < (unsigned)NTILES) { __nanosleep(100); }
        }
        __syncthreads();
        __threadfence();

        __shared__ float red[8];
        int b = blockIdx.x * 256 + tid;            // [0, 2048)
        float m1 = -1e30f, E1 = 0.0f, G1 = 0.0f;   // row b
        float m2 = -1e30f, E2 = 0.0f, G2 = 0.0f;   // row b+2048
#pragma unroll
        for (int s = 0; s < NB_; s++) {
            m1 = fmaxf(m1, g_Mp[s * NTOT + b]);
            E1 += g_Ep[s * NTOT + b];
            G1 += g_Gp[s * NTOT + b];
            m2 = fmaxf(m2, g_Mp[s * NTOT + B_ + b]);
            E2 += g_Ep[s * NTOT + B_ + b];
            G2 += g_Gp[s * NTOT + B_ + b];
        }
        const float invT = 1.0f / TEMP_F;
        // e^{m0 - m_i} with m0 = 1/T (raw ref 1.0): exp((1 - rawM)/T)
        float em1 = __expf((1.0f - m1) * invT);
        float em2 = __expf((1.0f - m2) * invT);
        float u_new = (1.0f - GAMMA_F) * u[index[b]] + GAMMA_F * em1 * E1;
        float t1 = em1 * invT * (G1 - m1 * E1) / u_new;
        float t2 = em2 * invT * (G2 - m2 * E2) / u_new;
        const float k = -(TEMP_F / BASET_F) * (1.0f / (float)NTOT);
        float val = k * ((invT * (g_SP[b]      - m1) - t1) +
                         (invT * (g_SP[B_ + b] - m2) - t2));
#pragma unroll
        for (int o = 16; o; o >>= 1) val += __shfl_down_sync(0xffffffffu, val, o);
        if ((tid & 31) == 0) red[tid >> 5] = val;
        __syncthreads();
        if (tid < 8) {
            float v = red[tid];
#pragma unroll
            for (int o = 4; o; o >>= 1) v += __shfl_down_sync(0xffu, v, o);
            if (tid == 0) {
                g_Lp[blockIdx.x] = v;
                __threadfence();
                unsigned int t = atomicAdd(&g_fin, 1u);
                if (t == 7u) {
                    float s = 0.0f;
#pragma unroll
                    for (int i = 0; i < 8; i++) s += g_Lp[i];
                    out[0] = s;
                    g_prep = 0;
                    g_ctr  = 0;
                    g_fin  = 0;
                }
            }
        }
    }
}

// ---------------- launch ----------------
extern "C" void kernel_launch(void* const* d_in, const int* in_sizes, int n_in,
                              void* d_out, int out_size) {
    const int*   d_index = nullptr;
    const float* d_feats = nullptr;
    const float* d_u     = nullptr;
    for (int i = 0; i < n_in; i++) {
        if (in_sizes[i] == B_)                 d_index = (const int*)d_in[i];
        else if (in_sizes[i] == B_ * V_ * D_)  d_feats = (const float*)d_in[i];
        else                                   d_u     = (const float*)d_in[i];
    }
    float* out = (float*)d_out;

    cudaFuncSetAttribute(fused_kernel,
                         cudaFuncAttributeMaxDynamicSharedMemorySize, SMEM_BYTES);

    fused_kernel<<<NTILES, 256, SMEM_BYTES>>>(d_feats, d_index, d_u, out);
}